// round 3
// baseline (speedup 1.0000x reference)
#include <cuda_runtime.h>
#include <cuda_bf16.h>
#include <math.h>

#define BB 16384
#define DD 512
#define HH 8192
#define KBK 16384

// ---------------- scratch ----------------
__device__ float g_exp[BB];
__device__ float g_bsum[KBK];
__device__ int   g_bcnt[KBK];
__device__ int   g_boff[KBK];
__device__ float g_sfx[KBK];
__device__ int   g_perm[BB];
__device__ float g_con[HH];
__device__ int   g_done = 0;

__device__ __forceinline__ int bucket_of(float t) {
    int b = (int)(t * 16384.0f);
    if (b < 0) b = 0;
    if (b > KBK - 1) b = KBK - 1;
    return b;
}

__device__ __forceinline__ float dot4(float4 x, float4 y) {
    return fmaf(x.x, y.x, fmaf(x.y, y.y, fmaf(x.z, y.z, x.w * y.w)));
}

// =====================================================================
// Single fused kernel. Block 0 = cox master (all phases, block-local
// sync only). Blocks 1..2048 = contrast, 4 pairs each. Master then
// waits for contrast completion and writes the scalar.
// =====================================================================
__global__ __launch_bounds__(512) void fused_kernel(
    const float* __restrict__ r1, const float* __restrict__ r2,
    const float* __restrict__ r3,
    const float* __restrict__ hazard, const float* __restrict__ time_,
    const int* __restrict__ event, const float* __restrict__ score,
    const int* __restrict__ x1, const int* __restrict__ x2,
    float* __restrict__ out)
{
    int blk = blockIdx.x, tid = threadIdx.x;
    int lane = tid & 31, warp = tid >> 5;

    if (blk == 0) {
        // =========================== COX MASTER ===========================
        __shared__ int   s_ci[16];
        __shared__ float s_cf[16];
        __shared__ float s_n[16], s_e[16], s_l[16], s_c[16];

        // ---- phase 1: exp + histogram (32 elems/thread) ----
#pragma unroll 4
        for (int r = 0; r < 32; r++) {
            int i = r * 512 + tid;
            float e = expf(hazard[i]);
            g_exp[i] = e;
            int b = bucket_of(time_[i]);
            atomicAdd(&g_bsum[b], e);
            atomicAdd(&g_bcnt[b], 1);
        }
        __threadfence_block();
        __syncthreads();

        // ---- phase 2: scan. warp w owns buckets [w*1024, (w+1)*1024) ----
        {
            int base = warp * 1024;
            int csum = 0; float fsum = 0.f;
            for (int r = 0; r < 32; r++) {
                int idx = base + r * 32 + lane;
                csum += g_bcnt[idx];
                fsum += g_bsum[idx];
            }
#pragma unroll
            for (int o = 16; o > 0; o >>= 1) {
                csum += __shfl_xor_sync(0xffffffffu, csum, o);
                fsum += __shfl_xor_sync(0xffffffffu, fsum, o);
            }
            if (lane == 0) { s_ci[warp] = csum; s_cf[warp] = fsum; }
            __syncthreads();

            int ibase = 0; float fsuf = 0.f;
            for (int w = 0; w < 16; w++) {
                if (w < warp) ibase += s_ci[w];
                if (w > warp) fsuf  += s_cf[w];
            }

            int icarry = ibase;
            for (int r = 0; r < 32; r++) {
                int idx = base + r * 32 + lane;
                int c = g_bcnt[idx];
                int inc = c;
#pragma unroll
                for (int o = 1; o < 32; o <<= 1) {
                    int u = __shfl_up_sync(0xffffffffu, inc, o);
                    if (lane >= o) inc += u;
                }
                g_boff[idx] = icarry + inc - c;
                icarry += __shfl_sync(0xffffffffu, inc, 31);
            }

            float fcarry = fsuf;
            for (int r = 31; r >= 0; r--) {
                int idx = base + r * 32 + lane;
                float v = g_bsum[idx];
                float incR = v;
#pragma unroll
                for (int o = 1; o < 32; o <<= 1) {
                    float u = __shfl_down_sync(0xffffffffu, incR, o);
                    if (lane < 32 - o) incR += u;
                }
                g_sfx[idx] = fcarry + incR - v;
                fcarry += __shfl_sync(0xffffffffu, incR, 0);
            }
        }
        __threadfence_block();
        __syncthreads();

        // ---- phase 3: scatter (cursor on g_boff; start recovered later) ----
#pragma unroll 4
        for (int r = 0; r < 32; r++) {
            int i = r * 512 + tid;
            int bkt = bucket_of(time_[i]);
            int slot = atomicAdd(&g_boff[bkt], 1);
            g_perm[slot] = i;
        }
        __threadfence_block();
        __syncthreads();

        // ---- phase 4: eval ----
        float num = 0.f, evs = 0.f, nll = 0.f;
        for (int r = 0; r < 32; r++) {
            int i = r * 512 + tid;
            float ti = time_[i];
            int bkt = bucket_of(ti);
            float S = g_sfx[bkt] + g_exp[i];
            int cnt = g_bcnt[bkt];
            int start = g_boff[bkt] - cnt;
            for (int s = start; s < start + cnt; s++) {
                int j = g_perm[s];
                if (j == i) continue;
                float tj = time_[j];
                if (tj > ti || (tj == ti && j < i)) S += g_exp[j];
            }
            float lr = logf(S + 1e-6f);
            int ev = event[i];
            float evf = (float)ev;
            num = fmaf(evf, hazard[i] - lr, num);
            evs += evf;
            nll += score[2 * i + ev];
        }
#pragma unroll
        for (int o = 16; o > 0; o >>= 1) {
            num += __shfl_xor_sync(0xffffffffu, num, o);
            evs += __shfl_xor_sync(0xffffffffu, evs, o);
            nll += __shfl_xor_sync(0xffffffffu, nll, o);
        }
        if (lane == 0) { s_n[warp] = num; s_e[warp] = evs; s_l[warp] = nll; }
        __syncthreads();

        // ---- phase 5: reset scratch for next graph replay ----
        for (int i = tid; i < KBK; i += 512) { g_bcnt[i] = 0; g_bsum[i] = 0.f; }

        // ---- phase 6: wait for contrast, final reduce ----
        if (tid == 0) {
            volatile int* p = &g_done;
            while (*p < 2048) __nanosleep(128);
        }
        __syncthreads();
        __threadfence();

        float cs = 0.f;
        for (int q = tid; q < HH; q += 512) cs += g_con[q];
#pragma unroll
        for (int o = 16; o > 0; o >>= 1) cs += __shfl_xor_sync(0xffffffffu, cs, o);
        if (lane == 0) s_c[warp] = cs;
        __syncthreads();

        if (tid == 0) {
            float CS = 0.f, PN = 0.f, PE = 0.f, PL = 0.f;
            for (int w = 0; w < 16; w++) {
                CS += s_c[w]; PN += s_n[w]; PE += s_e[w]; PL += s_l[w];
            }
            float nll_ = -PL / (float)BB;
            float cox  = -PN / (PE + 1e-6f);
            float con  = CS / (float)HH;
            out[0] = nll_ + cox + 0.3f * con;
            g_done = 0;
        }
        return;
    }

    // ============================ CONTRAST ============================
    __shared__ float s_red[16][15];

    int group = tid >> 7, gt = tid & 127;
    int m = (blk - 1) * 4 + group;
    int a = x1[m], b = x2[m];

    const float4* A1 = (const float4*)(r1 + (size_t)a * DD);
    const float4* A2 = (const float4*)(r2 + (size_t)a * DD);
    const float4* A3 = (const float4*)(r3 + (size_t)a * DD);
    const float4* B1 = (const float4*)(r1 + (size_t)b * DD);
    const float4* B2 = (const float4*)(r2 + (size_t)b * DD);
    const float4* B3 = (const float4*)(r3 + (size_t)b * DD);

    float4 a1 = A1[gt], a2 = A2[gt], a3 = A3[gt];
    float4 b1 = B1[gt], b2 = B2[gt], b3 = B3[gt];

    float acc[15];
    acc[0]  = dot4(a1, a1);  acc[1]  = dot4(a2, a2);  acc[2]  = dot4(a3, a3);
    acc[3]  = dot4(b1, b1);  acc[4]  = dot4(b2, b2);  acc[5]  = dot4(b3, b3);
    acc[6]  = dot4(a1, a2);  acc[7]  = dot4(a1, a3);  acc[8]  = dot4(a2, a3);
    acc[9]  = dot4(b1, b2);  acc[10] = dot4(b1, b3);  acc[11] = dot4(b2, b3);
    acc[12] = dot4(a1, b1);  acc[13] = dot4(a2, b2);  acc[14] = dot4(a3, b3);

#pragma unroll
    for (int q = 0; q < 15; q++) {
        float v = acc[q];
#pragma unroll
        for (int o = 16; o > 0; o >>= 1) v += __shfl_xor_sync(0xffffffffu, v, o);
        if (lane == 0) s_red[warp][q] = v;
    }
    __syncthreads();

    if (gt == 0) {
        int w0 = group * 4;
        float s[15];
#pragma unroll
        for (int q = 0; q < 15; q++)
            s[q] = s_red[w0][q] + s_red[w0+1][q] + s_red[w0+2][q] + s_red[w0+3][q];

        const float EPS = 1e-8f;
        float n1a = fmaxf(sqrtf(s[0]), EPS), n2a = fmaxf(sqrtf(s[1]), EPS), n3a = fmaxf(sqrtf(s[2]), EPS);
        float n1b = fmaxf(sqrtf(s[3]), EPS), n2b = fmaxf(sqrtf(s[4]), EPS), n3b = fmaxf(sqrtf(s[5]), EPS);

        float dis_xx = s[6] / (n1a * n2a) + s[7]  / (n1a * n3a) + s[8]  / (n2a * n3a);
        float dis_yy = s[9] / (n1b * n2b) + s[10] / (n1b * n3b) + s[11] / (n2b * n3b);
        float dis_xy = s[12] / (n1a * n1b) + s[13] / (n2a * n2b) + s[14] / (n3a * n3b);

        float z = 0.2f + dis_xy - 0.5f * dis_xx - 0.5f * dis_yy;
        float sp = (z > 0.f) ? (z + log1pf(expf(-z))) : log1pf(expf(z));
        g_con[m] = sp;
        __threadfence();
        atomicAdd(&g_done, 1);
    }
}

// ---------------- launch ----------------
extern "C" void kernel_launch(void* const* d_in, const int* in_sizes, int n_in,
                              void* d_out, int out_size) {
    const float* rep1   = (const float*)d_in[0];
    const float* rep2   = (const float*)d_in[1];
    const float* rep3   = (const float*)d_in[2];
    const float* hazard = (const float*)d_in[3];
    const float* score  = (const float*)d_in[4];
    const float* time_  = (const float*)d_in[5];
    const int*   event  = (const int*)d_in[6];
    const int*   x1_idx = (const int*)d_in[7];
    const int*   x2_idx = (const int*)d_in[8];
    float* out = (float*)d_out;

    fused_kernel<<<2049, 512>>>(rep1, rep2, rep3, hazard, time_,
                                event, score, x1_idx, x2_idx, out);
}

// round 4
// speedup vs baseline: 1.0666x; 1.0666x over previous
#include <cuda_runtime.h>
#include <cuda_bf16.h>
#include <math.h>

#define BB 16384
#define DD 512
#define HH 8192
#define KBK 16384

// ---------------- scratch ----------------
__device__ float g_exp[BB];
__device__ float g_bsum[KBK];
__device__ int   g_bcnt[KBK];
__device__ int   g_boff[KBK];
__device__ float g_sfx[KBK];
__device__ int   g_perm[BB];
__device__ float g_con[HH];
__device__ float g_part[3];     // num, evs, nll

__device__ __forceinline__ int bucket_of(float t) {
    int b = (int)(t * 16384.0f);
    if (b < 0) b = 0;
    if (b > KBK - 1) b = KBK - 1;
    return b;
}

__device__ __forceinline__ float dot4(float4 x, float4 y) {
    return fmaf(x.x, y.x, fmaf(x.y, y.y, fmaf(x.z, y.z, x.w * y.w)));
}

// =====================================================================
// K1: block 0 = full cox pipeline (block-local sync only, writes g_part).
//     blocks 1..2048 = contrast, 4 pairs each, write g_con. NO cross-
//     block synchronization anywhere.
// =====================================================================
__global__ __launch_bounds__(512, 3) void k1_kernel(
    const float* __restrict__ r1, const float* __restrict__ r2,
    const float* __restrict__ r3,
    const float* __restrict__ hazard, const float* __restrict__ time_,
    const int* __restrict__ event, const float* __restrict__ score,
    const int* __restrict__ x1, const int* __restrict__ x2)
{
    int blk = blockIdx.x, tid = threadIdx.x;
    int lane = tid & 31, warp = tid >> 5;

    if (blk == 0) {
        // =========================== COX MASTER ===========================
        __shared__ int   s_ci[16];
        __shared__ float s_cf[16];
        __shared__ float s_n[16], s_e[16], s_l[16];

        // ---- phase 1: exp + histogram ----
#pragma unroll 4
        for (int r = 0; r < 32; r++) {
            int i = r * 512 + tid;
            float e = expf(hazard[i]);
            g_exp[i] = e;
            int b = bucket_of(time_[i]);
            atomicAdd(&g_bsum[b], e);
            atomicAdd(&g_bcnt[b], 1);
        }
        __threadfence_block();
        __syncthreads();

        // ---- phase 2: scan. warp w owns buckets [w*1024, (w+1)*1024) ----
        {
            int base = warp * 1024;
            int csum = 0; float fsum = 0.f;
            for (int r = 0; r < 32; r++) {
                int idx = base + r * 32 + lane;
                csum += g_bcnt[idx];
                fsum += g_bsum[idx];
            }
#pragma unroll
            for (int o = 16; o > 0; o >>= 1) {
                csum += __shfl_xor_sync(0xffffffffu, csum, o);
                fsum += __shfl_xor_sync(0xffffffffu, fsum, o);
            }
            if (lane == 0) { s_ci[warp] = csum; s_cf[warp] = fsum; }
            __syncthreads();

            int ibase = 0; float fsuf = 0.f;
            for (int w = 0; w < 16; w++) {
                if (w < warp) ibase += s_ci[w];
                if (w > warp) fsuf  += s_cf[w];
            }

            int icarry = ibase;
            for (int r = 0; r < 32; r++) {
                int idx = base + r * 32 + lane;
                int c = g_bcnt[idx];
                int inc = c;
#pragma unroll
                for (int o = 1; o < 32; o <<= 1) {
                    int u = __shfl_up_sync(0xffffffffu, inc, o);
                    if (lane >= o) inc += u;
                }
                g_boff[idx] = icarry + inc - c;
                icarry += __shfl_sync(0xffffffffu, inc, 31);
            }

            float fcarry = fsuf;
            for (int r = 31; r >= 0; r--) {
                int idx = base + r * 32 + lane;
                float v = g_bsum[idx];
                float incR = v;
#pragma unroll
                for (int o = 1; o < 32; o <<= 1) {
                    float u = __shfl_down_sync(0xffffffffu, incR, o);
                    if (lane < 32 - o) incR += u;
                }
                g_sfx[idx] = fcarry + incR - v;
                fcarry += __shfl_sync(0xffffffffu, incR, 0);
            }
        }
        __threadfence_block();
        __syncthreads();

        // ---- phase 3: scatter (g_boff becomes end-cursor) ----
#pragma unroll 4
        for (int r = 0; r < 32; r++) {
            int i = r * 512 + tid;
            int bkt = bucket_of(time_[i]);
            int slot = atomicAdd(&g_boff[bkt], 1);
            g_perm[slot] = i;
        }
        __threadfence_block();
        __syncthreads();

        // ---- phase 4: eval ----
        float num = 0.f, evs = 0.f, nll = 0.f;
        for (int r = 0; r < 32; r++) {
            int i = r * 512 + tid;
            float ti = time_[i];
            int bkt = bucket_of(ti);
            float S = g_sfx[bkt] + g_exp[i];
            int cnt = g_bcnt[bkt];
            int start = g_boff[bkt] - cnt;
            for (int s = start; s < start + cnt; s++) {
                int j = g_perm[s];
                if (j == i) continue;
                float tj = time_[j];
                if (tj > ti || (tj == ti && j < i)) S += g_exp[j];
            }
            float lr = logf(S + 1e-6f);
            int ev = event[i];
            float evf = (float)ev;
            num = fmaf(evf, hazard[i] - lr, num);
            evs += evf;
            nll += score[2 * i + ev];
        }
#pragma unroll
        for (int o = 16; o > 0; o >>= 1) {
            num += __shfl_xor_sync(0xffffffffu, num, o);
            evs += __shfl_xor_sync(0xffffffffu, evs, o);
            nll += __shfl_xor_sync(0xffffffffu, nll, o);
        }
        if (lane == 0) { s_n[warp] = num; s_e[warp] = evs; s_l[warp] = nll; }
        __syncthreads();

        // ---- phase 5: reset scratch + write partials ----
        for (int i = tid; i < KBK; i += 512) { g_bcnt[i] = 0; g_bsum[i] = 0.f; }
        if (tid == 0) {
            float PN = 0.f, PE = 0.f, PL = 0.f;
            for (int w = 0; w < 16; w++) { PN += s_n[w]; PE += s_e[w]; PL += s_l[w]; }
            g_part[0] = PN; g_part[1] = PE; g_part[2] = PL;
        }
        return;
    }

    // ============================ CONTRAST ============================
    __shared__ float s_red[16][15];

    int group = tid >> 7, gt = tid & 127;
    int m = (blk - 1) * 4 + group;
    int a = x1[m], b = x2[m];

    const float4* A1 = (const float4*)(r1 + (size_t)a * DD);
    const float4* A2 = (const float4*)(r2 + (size_t)a * DD);
    const float4* A3 = (const float4*)(r3 + (size_t)a * DD);
    const float4* B1 = (const float4*)(r1 + (size_t)b * DD);
    const float4* B2 = (const float4*)(r2 + (size_t)b * DD);
    const float4* B3 = (const float4*)(r3 + (size_t)b * DD);

    float4 a1 = A1[gt], a2 = A2[gt], a3 = A3[gt];
    float4 b1 = B1[gt], b2 = B2[gt], b3 = B3[gt];

    float acc[15];
    acc[0]  = dot4(a1, a1);  acc[1]  = dot4(a2, a2);  acc[2]  = dot4(a3, a3);
    acc[3]  = dot4(b1, b1);  acc[4]  = dot4(b2, b2);  acc[5]  = dot4(b3, b3);
    acc[6]  = dot4(a1, a2);  acc[7]  = dot4(a1, a3);  acc[8]  = dot4(a2, a3);
    acc[9]  = dot4(b1, b2);  acc[10] = dot4(b1, b3);  acc[11] = dot4(b2, b3);
    acc[12] = dot4(a1, b1);  acc[13] = dot4(a2, b2);  acc[14] = dot4(a3, b3);

#pragma unroll
    for (int q = 0; q < 15; q++) {
        float v = acc[q];
#pragma unroll
        for (int o = 16; o > 0; o >>= 1) v += __shfl_xor_sync(0xffffffffu, v, o);
        if (lane == 0) s_red[warp][q] = v;
    }
    __syncthreads();

    if (gt == 0) {
        int w0 = group * 4;
        float s[15];
#pragma unroll
        for (int q = 0; q < 15; q++)
            s[q] = s_red[w0][q] + s_red[w0+1][q] + s_red[w0+2][q] + s_red[w0+3][q];

        const float EPS = 1e-8f;
        float n1a = fmaxf(sqrtf(s[0]), EPS), n2a = fmaxf(sqrtf(s[1]), EPS), n3a = fmaxf(sqrtf(s[2]), EPS);
        float n1b = fmaxf(sqrtf(s[3]), EPS), n2b = fmaxf(sqrtf(s[4]), EPS), n3b = fmaxf(sqrtf(s[5]), EPS);

        float dis_xx = s[6] / (n1a * n2a) + s[7]  / (n1a * n3a) + s[8]  / (n2a * n3a);
        float dis_yy = s[9] / (n1b * n2b) + s[10] / (n1b * n3b) + s[11] / (n2b * n3b);
        float dis_xy = s[12] / (n1a * n1b) + s[13] / (n2a * n2b) + s[14] / (n3a * n3b);

        float z = 0.2f + dis_xy - 0.5f * dis_xx - 0.5f * dis_yy;
        float sp = (z > 0.f) ? (z + log1pf(expf(-z))) : log1pf(expf(z));
        g_con[m] = sp;
    }
}

// =====================================================================
// K2: single block final reduce. Kernel boundary = synchronization.
// =====================================================================
__global__ __launch_bounds__(512) void k2_kernel(float* __restrict__ out) {
    __shared__ float s_c[16];
    int tid = threadIdx.x, lane = tid & 31, warp = tid >> 5;

    float cs = 0.f;
#pragma unroll
    for (int r = 0; r < 16; r++) cs += g_con[r * 512 + tid];
#pragma unroll
    for (int o = 16; o > 0; o >>= 1) cs += __shfl_xor_sync(0xffffffffu, cs, o);
    if (lane == 0) s_c[warp] = cs;
    __syncthreads();

    if (tid == 0) {
        float CS = 0.f;
        for (int w = 0; w < 16; w++) CS += s_c[w];
        float PN = g_part[0], PE = g_part[1], PL = g_part[2];
        float nll_ = -PL / (float)BB;
        float cox  = -PN / (PE + 1e-6f);
        float con  = CS / (float)HH;
        out[0] = nll_ + cox + 0.3f * con;
    }
}

// ---------------- launch ----------------
extern "C" void kernel_launch(void* const* d_in, const int* in_sizes, int n_in,
                              void* d_out, int out_size) {
    const float* rep1   = (const float*)d_in[0];
    const float* rep2   = (const float*)d_in[1];
    const float* rep3   = (const float*)d_in[2];
    const float* hazard = (const float*)d_in[3];
    const float* score  = (const float*)d_in[4];
    const float* time_  = (const float*)d_in[5];
    const int*   event  = (const int*)d_in[6];
    const int*   x1_idx = (const int*)d_in[7];
    const int*   x2_idx = (const int*)d_in[8];
    float* out = (float*)d_out;

    k1_kernel<<<2049, 512>>>(rep1, rep2, rep3, hazard, time_,
                             event, score, x1_idx, x2_idx);
    k2_kernel<<<1, 512>>>(out);
}

// round 5
// speedup vs baseline: 2.7689x; 2.5960x over previous
#include <cuda_runtime.h>
#include <cuda_bf16.h>
#include <math.h>

#define BB 16384
#define DD 512
#define HH 8192
#define KBK 16384

// ---------------- scratch ----------------
__device__ float g_exp[BB];
__device__ float g_bsum[KBK];
__device__ int   g_bcnt[KBK];
__device__ int   g_boff[KBK];      // after K1: end-cursor (start = end - cnt)
__device__ float g_sfx[KBK];
__device__ int   g_perm[BB];
__device__ float g_con[HH];
__device__ float g_part[256];      // [0:64) num, [64:128) evs, [128:192) nll, [192:256) con
__device__ int   g_cnt_done  = 0;
__device__ int   g_eval_done = 0;

__device__ __forceinline__ int bucket_of(float t) {
    int b = (int)(t * 16384.0f);
    if (b < 0) b = 0;
    if (b > KBK - 1) b = KBK - 1;
    return b;
}

__device__ __forceinline__ float dot4(float4 x, float4 y) {
    return fmaf(x.x, y.x, fmaf(x.y, y.y, fmaf(x.z, y.z, x.w * y.w)));
}

// =====================================================================
// K1: block 0 = master (wait feeders -> scan -> scatter).
//     blocks 1..64 = histogram feeders, then contrast.
//     blocks 1..2048 = contrast, 4 pairs each.
// =====================================================================
__global__ __launch_bounds__(512) void k1_kernel(
    const float* __restrict__ r1, const float* __restrict__ r2,
    const float* __restrict__ r3,
    const float* __restrict__ hazard, const float* __restrict__ time_,
    const int* __restrict__ x1, const int* __restrict__ x2)
{
    int blk = blockIdx.x, tid = threadIdx.x;
    int lane = tid & 31, warp = tid >> 5;

    __shared__ float s_red[16][15];
    __shared__ int   s_ci[16];
    __shared__ float s_cf[16];

    if (blk == 0) {
        // ---- wait for all 64 histogram feeders ----
        if (tid == 0) {
            volatile int* p = &g_cnt_done;
            while (*p < 64) __nanosleep(64);
            g_cnt_done = 0;
        }
        __syncthreads();
        __threadfence();

        // ---- scan: warp w owns buckets [w*1024, (w+1)*1024) ----
        int base = warp * 1024;
        int csum = 0; float fsum = 0.f;
        for (int r = 0; r < 32; r++) {
            int idx = base + r * 32 + lane;
            csum += g_bcnt[idx];
            fsum += g_bsum[idx];
        }
#pragma unroll
        for (int o = 16; o > 0; o >>= 1) {
            csum += __shfl_xor_sync(0xffffffffu, csum, o);
            fsum += __shfl_xor_sync(0xffffffffu, fsum, o);
        }
        if (lane == 0) { s_ci[warp] = csum; s_cf[warp] = fsum; }
        __syncthreads();

        int ibase = 0; float fsuf = 0.f;
        for (int w = 0; w < 16; w++) {
            if (w < warp) ibase += s_ci[w];
            if (w > warp) fsuf  += s_cf[w];
        }

        int icarry = ibase;
        for (int r = 0; r < 32; r++) {
            int idx = base + r * 32 + lane;
            int c = g_bcnt[idx];
            int inc = c;
#pragma unroll
            for (int o = 1; o < 32; o <<= 1) {
                int u = __shfl_up_sync(0xffffffffu, inc, o);
                if (lane >= o) inc += u;
            }
            g_boff[idx] = icarry + inc - c;
            icarry += __shfl_sync(0xffffffffu, inc, 31);
        }

        float fcarry = fsuf;
        for (int r = 31; r >= 0; r--) {
            int idx = base + r * 32 + lane;
            float v = g_bsum[idx];
            float incR = v;
#pragma unroll
            for (int o = 1; o < 32; o <<= 1) {
                float u = __shfl_down_sync(0xffffffffu, incR, o);
                if (lane < 32 - o) incR += u;
            }
            g_sfx[idx] = fcarry + incR - v;
            fcarry += __shfl_sync(0xffffffffu, incR, 0);
        }
        __threadfence_block();
        __syncthreads();

        // ---- scatter (g_boff becomes end-cursor) ----
#pragma unroll 4
        for (int r = 0; r < 32; r++) {
            int i = r * 512 + tid;
            int bkt = bucket_of(time_[i]);
            int slot = atomicAdd(&g_boff[bkt], 1);
            g_perm[slot] = i;
        }

        // ---- reset bsum for next replay (bcnt still needed by K2) ----
        for (int i = tid; i < KBK; i += 512) g_bsum[i] = 0.f;
        return;
    }

    // ---- histogram feeders: blocks 1..64, 256 elements each ----
    if (blk <= 64) {
        if (tid < 256) {
            int i = (blk - 1) * 256 + tid;
            float e = expf(hazard[i]);
            g_exp[i] = e;
            int b = bucket_of(time_[i]);
            atomicAdd(&g_bsum[b], e);
            atomicAdd(&g_bcnt[b], 1);
        }
        __threadfence();
        __syncthreads();
        if (tid == 0) atomicAdd(&g_cnt_done, 1);
    }

    // ---- contrast: 4 pairs per block, 128 threads per pair ----
    int group = tid >> 7, gt = tid & 127;
    int m = (blk - 1) * 4 + group;
    int a = x1[m], b = x2[m];

    const float4* A1 = (const float4*)(r1 + (size_t)a * DD);
    const float4* A2 = (const float4*)(r2 + (size_t)a * DD);
    const float4* A3 = (const float4*)(r3 + (size_t)a * DD);
    const float4* B1 = (const float4*)(r1 + (size_t)b * DD);
    const float4* B2 = (const float4*)(r2 + (size_t)b * DD);
    const float4* B3 = (const float4*)(r3 + (size_t)b * DD);

    float4 a1 = A1[gt], a2 = A2[gt], a3 = A3[gt];
    float4 b1 = B1[gt], b2 = B2[gt], b3 = B3[gt];

    float acc[15];
    acc[0]  = dot4(a1, a1);  acc[1]  = dot4(a2, a2);  acc[2]  = dot4(a3, a3);
    acc[3]  = dot4(b1, b1);  acc[4]  = dot4(b2, b2);  acc[5]  = dot4(b3, b3);
    acc[6]  = dot4(a1, a2);  acc[7]  = dot4(a1, a3);  acc[8]  = dot4(a2, a3);
    acc[9]  = dot4(b1, b2);  acc[10] = dot4(b1, b3);  acc[11] = dot4(b2, b3);
    acc[12] = dot4(a1, b1);  acc[13] = dot4(a2, b2);  acc[14] = dot4(a3, b3);

#pragma unroll
    for (int q = 0; q < 15; q++) {
        float v = acc[q];
#pragma unroll
        for (int o = 16; o > 0; o >>= 1) v += __shfl_xor_sync(0xffffffffu, v, o);
        if (lane == 0) s_red[warp][q] = v;
    }
    __syncthreads();

    if (gt == 0) {
        int w0 = group * 4;
        float s[15];
#pragma unroll
        for (int q = 0; q < 15; q++)
            s[q] = s_red[w0][q] + s_red[w0+1][q] + s_red[w0+2][q] + s_red[w0+3][q];

        const float EPS = 1e-8f;
        float n1a = fmaxf(sqrtf(s[0]), EPS), n2a = fmaxf(sqrtf(s[1]), EPS), n3a = fmaxf(sqrtf(s[2]), EPS);
        float n1b = fmaxf(sqrtf(s[3]), EPS), n2b = fmaxf(sqrtf(s[4]), EPS), n3b = fmaxf(sqrtf(s[5]), EPS);

        float dis_xx = s[6] / (n1a * n2a) + s[7]  / (n1a * n3a) + s[8]  / (n2a * n3a);
        float dis_yy = s[9] / (n1b * n2b) + s[10] / (n1b * n3b) + s[11] / (n2b * n3b);
        float dis_xy = s[12] / (n1a * n1b) + s[13] / (n2a * n2b) + s[14] / (n3a * n3b);

        float z = 0.2f + dis_xy - 0.5f * dis_xx - 0.5f * dis_yy;
        float sp = (z > 0.f) ? (z + log1pf(expf(-z))) : log1pf(expf(z));
        g_con[m] = sp;
    }
}

// =====================================================================
// K2: 64 blocks x 256, barrier-free. Each block: con slice + eval 256
//     elements -> 4 partials. Last finisher reduces 64x4 partials.
// =====================================================================
__global__ __launch_bounds__(256) void k2_kernel(
    const float* __restrict__ hazard, const float* __restrict__ time_,
    const int* __restrict__ event, const float* __restrict__ score,
    float* __restrict__ out)
{
    int blk = blockIdx.x, tid = threadIdx.x;
    int lane = tid & 31, warp = tid >> 5;
    int i = blk * 256 + tid;

    __shared__ int   s_go;
    __shared__ float s_n[8], s_e[8], s_l[8], s_c[8];

    // ---- con slice: 128 elements per block (tid<128) ----
    float cs = 0.f;
    if (tid < 128) cs = g_con[blk * 128 + tid];

    // ---- eval: 1 element per thread ----
    float ti = time_[i];
    int bkt = bucket_of(ti);
    float S = g_sfx[bkt] + g_exp[i];
    int cnt = g_bcnt[bkt];
    int start = g_boff[bkt] - cnt;
    for (int s = start; s < start + cnt; s++) {
        int j = g_perm[s];
        if (j == i) continue;
        float tj = time_[j];
        if (tj > ti || (tj == ti && j < i)) S += g_exp[j];
    }
    float lr = logf(S + 1e-6f);
    int ev = event[i];
    float evf = (float)ev;
    float num = evf * (hazard[i] - lr);
    float evs = evf;
    float nll = score[2 * i + ev];

#pragma unroll
    for (int o = 16; o > 0; o >>= 1) {
        num += __shfl_xor_sync(0xffffffffu, num, o);
        evs += __shfl_xor_sync(0xffffffffu, evs, o);
        nll += __shfl_xor_sync(0xffffffffu, nll, o);
        cs  += __shfl_xor_sync(0xffffffffu, cs,  o);
    }
    if (lane == 0) { s_n[warp] = num; s_e[warp] = evs; s_l[warp] = nll; s_c[warp] = cs; }
    __syncthreads();

    if (tid == 0) {
        float a = 0.f, b = 0.f, c = 0.f, d = 0.f;
        for (int w = 0; w < 8; w++) { a += s_n[w]; b += s_e[w]; c += s_l[w]; d += s_c[w]; }
        g_part[blk]       = a;
        g_part[64 + blk]  = b;
        g_part[128 + blk] = c;
        g_part[192 + blk] = d;
        __threadfence();
        int old = atomicAdd(&g_eval_done, 1);
        s_go = (old == 63) ? 1 : 0;
    }
    __syncthreads();

    // ---- finisher ----
    if (s_go) {
        __threadfence();
        // reset bcnt + done flag for next replay
        for (int b2 = tid; b2 < KBK; b2 += 256) g_bcnt[b2] = 0;

        float pn = 0.f, pe = 0.f, pl = 0.f, pc = 0.f;
        if (tid < 64) {
            pn = g_part[tid];
            pe = g_part[64 + tid];
            pl = g_part[128 + tid];
            pc = g_part[192 + tid];
        }
#pragma unroll
        for (int o = 16; o > 0; o >>= 1) {
            pn += __shfl_xor_sync(0xffffffffu, pn, o);
            pe += __shfl_xor_sync(0xffffffffu, pe, o);
            pl += __shfl_xor_sync(0xffffffffu, pl, o);
            pc += __shfl_xor_sync(0xffffffffu, pc, o);
        }
        if (lane == 0) { s_n[warp] = pn; s_e[warp] = pe; s_l[warp] = pl; s_c[warp] = pc; }
        __syncthreads();
        if (tid == 0) {
            float PN = 0.f, PE = 0.f, PL = 0.f, PC = 0.f;
            for (int w = 0; w < 2; w++) {
                PN += s_n[w]; PE += s_e[w]; PL += s_l[w]; PC += s_c[w];
            }
            float nll_ = -PL / (float)BB;
            float cox  = -PN / (PE + 1e-6f);
            float con  = PC / (float)HH;
            out[0] = nll_ + cox + 0.3f * con;
            g_eval_done = 0;
        }
    }
}

// ---------------- launch ----------------
extern "C" void kernel_launch(void* const* d_in, const int* in_sizes, int n_in,
                              void* d_out, int out_size) {
    const float* rep1   = (const float*)d_in[0];
    const float* rep2   = (const float*)d_in[1];
    const float* rep3   = (const float*)d_in[2];
    const float* hazard = (const float*)d_in[3];
    const float* score  = (const float*)d_in[4];
    const float* time_  = (const float*)d_in[5];
    const int*   event  = (const int*)d_in[6];
    const int*   x1_idx = (const int*)d_in[7];
    const int*   x2_idx = (const int*)d_in[8];
    float* out = (float*)d_out;

    k1_kernel<<<2049, 512>>>(rep1, rep2, rep3, hazard, time_, x1_idx, x2_idx);
    k2_kernel<<<64, 256>>>(hazard, time_, event, score, out);
}

// round 7
// speedup vs baseline: 4.0199x; 1.4518x over previous
#include <cuda_runtime.h>
#include <cuda_bf16.h>
#include <math.h>

#define BB 16384
#define DD 512
#define HH 8192
#define KBK 16384

// ---------------- scratch ----------------
__device__ float g_exp[BB];
__device__ float g_bsum[KBK];
__device__ int   g_bcnt[KBK];
__device__ int   g_boff[KBK];      // master writes start; feeders advance to end
__device__ int2  g_pack[KBK];      // {sfx bits, start | cnt<<16}
__device__ int   g_perm[BB];
__device__ float g_con[HH];
__device__ float g_part[256];      // [0:64) num, [64:128) evs, [128:192) nll, [192:256) con
__device__ int   g_cnt_done  = 0;
__device__ int   g_scan_done = 0;
__device__ int   g_eval_done = 0;

__device__ __forceinline__ int bucket_of(float t) {
    int b = (int)(t * 16384.0f);
    if (b < 0) b = 0;
    if (b > KBK - 1) b = KBK - 1;
    return b;
}

__device__ __forceinline__ float dot4(float4 x, float4 y) {
    return fmaf(x.x, y.x, fmaf(x.y, y.y, fmaf(x.z, y.z, x.w * y.w)));
}

// =====================================================================
// K1: block 0 = master (wait feeders -> scan -> pack -> zero -> flag).
//     blocks 1..64 = histogram feeders -> contrast -> scatter.
//     blocks 1..2048 = contrast, 4 pairs each (__ldcs streaming loads).
// =====================================================================
__global__ __launch_bounds__(512) void k1_kernel(
    const float* __restrict__ r1, const float* __restrict__ r2,
    const float* __restrict__ r3,
    const float* __restrict__ hazard, const float* __restrict__ time_,
    const int* __restrict__ x1, const int* __restrict__ x2)
{
    int blk = blockIdx.x, tid = threadIdx.x;
    int lane = tid & 31, warp = tid >> 5;

    __shared__ float s_red[16][15];
    __shared__ int   s_ci[16];
    __shared__ float s_cf[16];

    if (blk == 0) {
        // ---- wait for the 64 histogram feeders ----
        if (tid == 0) {
            volatile int* p = &g_cnt_done;
            while (*p < 64) __nanosleep(64);
            g_cnt_done = 0;
        }
        __syncthreads();
        __threadfence();

        // warp w owns buckets [w*1024, (w+1)*1024)
        int base = warp * 1024;

        // ---- sweep A: warp totals ----
        int csum = 0; float fsum = 0.f;
        for (int r = 0; r < 32; r++) {
            int idx = base + r * 32 + lane;
            csum += g_bcnt[idx];
            fsum += g_bsum[idx];
        }
#pragma unroll
        for (int o = 16; o > 0; o >>= 1) {
            csum += __shfl_xor_sync(0xffffffffu, csum, o);
            fsum += __shfl_xor_sync(0xffffffffu, fsum, o);
        }
        if (lane == 0) { s_ci[warp] = csum; s_cf[warp] = fsum; }
        __syncthreads();

        int ibase = 0; float fsuf = 0.f;
        for (int w = 0; w < 16; w++) {
            if (w < warp) ibase += s_ci[w];
            if (w > warp) fsuf  += s_cf[w];
        }

        // ---- sweep B: exclusive prefix of counts -> g_boff (start) ----
        int icarry = ibase;
        for (int r = 0; r < 32; r++) {
            int idx = base + r * 32 + lane;
            int c = g_bcnt[idx];
            int inc = c;
#pragma unroll
            for (int o = 1; o < 32; o <<= 1) {
                int u = __shfl_up_sync(0xffffffffu, inc, o);
                if (lane >= o) inc += u;
            }
            g_boff[idx] = icarry + inc - c;
            icarry += __shfl_sync(0xffffffffu, inc, 31);
        }

        // ---- sweep C (reverse): strict suffix of bsum -> pack, zero scratch ----
        float fcarry = fsuf;
        for (int r = 31; r >= 0; r--) {
            int idx = base + r * 32 + lane;
            float v = g_bsum[idx];
            float incR = v;
#pragma unroll
            for (int o = 1; o < 32; o <<= 1) {
                float u = __shfl_down_sync(0xffffffffu, incR, o);
                if (lane < 32 - o) incR += u;
            }
            float sfx = fcarry + incR - v;
            int cnt   = g_bcnt[idx];
            int start = g_boff[idx];
            int2 pk;
            pk.x = __float_as_int(sfx);
            pk.y = start | (cnt << 16);
            g_pack[idx] = pk;
            g_bcnt[idx] = 0;
            g_bsum[idx] = 0.f;
            fcarry += __shfl_sync(0xffffffffu, incR, 0);
        }
        __syncthreads();
        __threadfence();
        if (tid == 0) g_scan_done = 1;
        return;
    }

    // ---- histogram feeders: blocks 1..64, 256 elements each ----
    if (blk <= 64) {
        if (tid < 256) {
            int i = (blk - 1) * 256 + tid;
            float e = expf(hazard[i]);
            g_exp[i] = e;
            int b = bucket_of(time_[i]);
            atomicAdd(&g_bsum[b], e);
            atomicAdd(&g_bcnt[b], 1);
        }
        __threadfence();
        __syncthreads();
        if (tid == 0) atomicAdd(&g_cnt_done, 1);
    }

    // ---- contrast: 4 pairs per block, 128 threads per pair ----
    {
        int group = tid >> 7, gt = tid & 127;
        int m = (blk - 1) * 4 + group;
        int a = x1[m], b = x2[m];

        const float4* A1 = (const float4*)(r1 + (size_t)a * DD);
        const float4* A2 = (const float4*)(r2 + (size_t)a * DD);
        const float4* A3 = (const float4*)(r3 + (size_t)a * DD);
        const float4* B1 = (const float4*)(r1 + (size_t)b * DD);
        const float4* B2 = (const float4*)(r2 + (size_t)b * DD);
        const float4* B3 = (const float4*)(r3 + (size_t)b * DD);

        float4 a1 = __ldcs(&A1[gt]), a2 = __ldcs(&A2[gt]), a3 = __ldcs(&A3[gt]);
        float4 b1 = __ldcs(&B1[gt]), b2 = __ldcs(&B2[gt]), b3 = __ldcs(&B3[gt]);

        float acc[15];
        acc[0]  = dot4(a1, a1);  acc[1]  = dot4(a2, a2);  acc[2]  = dot4(a3, a3);
        acc[3]  = dot4(b1, b1);  acc[4]  = dot4(b2, b2);  acc[5]  = dot4(b3, b3);
        acc[6]  = dot4(a1, a2);  acc[7]  = dot4(a1, a3);  acc[8]  = dot4(a2, a3);
        acc[9]  = dot4(b1, b2);  acc[10] = dot4(b1, b3);  acc[11] = dot4(b2, b3);
        acc[12] = dot4(a1, b1);  acc[13] = dot4(a2, b2);  acc[14] = dot4(a3, b3);

#pragma unroll
        for (int q = 0; q < 15; q++) {
            float v = acc[q];
#pragma unroll
            for (int o = 16; o > 0; o >>= 1) v += __shfl_xor_sync(0xffffffffu, v, o);
            if (lane == 0) s_red[warp][q] = v;
        }
        __syncthreads();

        if (gt == 0) {
            int w0 = group * 4;
            float s[15];
#pragma unroll
            for (int q = 0; q < 15; q++)
                s[q] = s_red[w0][q] + s_red[w0+1][q] + s_red[w0+2][q] + s_red[w0+3][q];

            const float EPS = 1e-8f;
            float n1a = fmaxf(sqrtf(s[0]), EPS), n2a = fmaxf(sqrtf(s[1]), EPS), n3a = fmaxf(sqrtf(s[2]), EPS);
            float n1b = fmaxf(sqrtf(s[3]), EPS), n2b = fmaxf(sqrtf(s[4]), EPS), n3b = fmaxf(sqrtf(s[5]), EPS);

            float dis_xx = s[6] / (n1a * n2a) + s[7]  / (n1a * n3a) + s[8]  / (n2a * n3a);
            float dis_yy = s[9] / (n1b * n2b) + s[10] / (n1b * n3b) + s[11] / (n2b * n3b);
            float dis_xy = s[12] / (n1a * n1b) + s[13] / (n2a * n2b) + s[14] / (n3a * n3b);

            float z = 0.2f + dis_xy - 0.5f * dis_xx - 0.5f * dis_yy;
            float sp = (z > 0.f) ? (z + log1pf(expf(-z))) : log1pf(expf(z));
            g_con[m] = sp;
        }
    }

    // ---- feeders: scatter after contrast (scan long done -> spin ~0) ----
    if (blk <= 64) {
        if (tid == 0) {
            volatile int* p = &g_scan_done;
            while (*p == 0) __nanosleep(64);
        }
        __syncthreads();
        __threadfence();
        if (tid < 256) {
            int i = (blk - 1) * 256 + tid;
            int bkt = bucket_of(time_[i]);
            int slot = atomicAdd(&g_boff[bkt], 1);
            g_perm[slot] = i;
        }
    }
}

// =====================================================================
// K2: 64 blocks x 256, eval-only + con partials; finisher combines.
// =====================================================================
__global__ __launch_bounds__(256) void k2_kernel(
    const float* __restrict__ hazard, const float* __restrict__ time_,
    const int* __restrict__ event, const float* __restrict__ score,
    float* __restrict__ out)
{
    int blk = blockIdx.x, tid = threadIdx.x;
    int lane = tid & 31, warp = tid >> 5;
    int i = blk * 256 + tid;

    __shared__ int   s_go;
    __shared__ float s_n[8], s_e[8], s_l[8], s_c[8];

    // con slice: 128 elements per block
    float cs = 0.f;
    if (tid < 128) cs = g_con[blk * 128 + tid];

    // eval: 1 element per thread
    float ti = time_[i];
    int bkt = bucket_of(ti);
    int2 pk = g_pack[bkt];
    float S = __int_as_float(pk.x) + g_exp[i];
    int start = pk.y & 0xffff;
    int cnt   = pk.y >> 16;
    if (cnt > 1) {
        for (int s = start; s < start + cnt; s++) {
            int j = g_perm[s];
            if (j == i) continue;
            float tj = time_[j];
            if (tj > ti || (tj == ti && j < i)) S += g_exp[j];
        }
    }
    float lr = logf(S + 1e-6f);
    int ev = event[i];
    float evf = (float)ev;
    float num = evf * (hazard[i] - lr);
    float evs = evf;
    float nll = score[2 * i + ev];

#pragma unroll
    for (int o = 16; o > 0; o >>= 1) {
        num += __shfl_xor_sync(0xffffffffu, num, o);
        evs += __shfl_xor_sync(0xffffffffu, evs, o);
        nll += __shfl_xor_sync(0xffffffffu, nll, o);
        cs  += __shfl_xor_sync(0xffffffffu, cs,  o);
    }
    if (lane == 0) { s_n[warp] = num; s_e[warp] = evs; s_l[warp] = nll; s_c[warp] = cs; }
    __syncthreads();

    if (tid == 0) {
        float a = 0.f, b = 0.f, c = 0.f, d = 0.f;
        for (int w = 0; w < 8; w++) { a += s_n[w]; b += s_e[w]; c += s_l[w]; d += s_c[w]; }
        g_part[blk]       = a;
        g_part[64 + blk]  = b;
        g_part[128 + blk] = c;
        g_part[192 + blk] = d;
        __threadfence();
        int old = atomicAdd(&g_eval_done, 1);
        s_go = (old == 63) ? 1 : 0;
    }
    __syncthreads();

    // ---- finisher: combine 64 partials, write scalar, reset flags ----
    if (s_go) {
        __threadfence();
        float pn = 0.f, pe = 0.f, pl = 0.f, pc = 0.f;
        if (tid < 64) {
            pn = g_part[tid];
            pe = g_part[64 + tid];
            pl = g_part[128 + tid];
            pc = g_part[192 + tid];
        }
#pragma unroll
        for (int o = 16; o > 0; o >>= 1) {
            pn += __shfl_xor_sync(0xffffffffu, pn, o);
            pe += __shfl_xor_sync(0xffffffffu, pe, o);
            pl += __shfl_xor_sync(0xffffffffu, pl, o);
            pc += __shfl_xor_sync(0xffffffffu, pc, o);
        }
        if (lane == 0) { s_n[warp] = pn; s_e[warp] = pe; s_l[warp] = pl; s_c[warp] = pc; }
        __syncthreads();
        if (tid == 0) {
            float PN = s_n[0] + s_n[1], PE = s_e[0] + s_e[1];
            float PL = s_l[0] + s_l[1], PC = s_c[0] + s_c[1];
            float nll_ = -PL / (float)BB;
            float cox  = -PN / (PE + 1e-6f);
            float con  = PC / (float)HH;
            out[0] = nll_ + cox + 0.3f * con;
            g_eval_done = 0;
            g_scan_done = 0;
        }
    }
}

// ---------------- launch ----------------
extern "C" void kernel_launch(void* const* d_in, const int* in_sizes, int n_in,
                              void* d_out, int out_size) {
    const float* rep1   = (const float*)d_in[0];
    const float* rep2   = (const float*)d_in[1];
    const float* rep3   = (const float*)d_in[2];
    const float* hazard = (const float*)d_in[3];
    const float* score  = (const float*)d_in[4];
    const float* time_  = (const float*)d_in[5];
    const int*   event  = (const int*)d_in[6];
    const int*   x1_idx = (const int*)d_in[7];
    const int*   x2_idx = (const int*)d_in[8];
    float* out = (float*)d_out;

    k1_kernel<<<2049, 512>>>(rep1, rep2, rep3, hazard, time_, x1_idx, x2_idx);
    k2_kernel<<<64, 256>>>(hazard, time_, event, score, out);
}

// round 8
// speedup vs baseline: 4.4056x; 1.0960x over previous
#include <cuda_runtime.h>
#include <cuda_bf16.h>
#include <math.h>

#define BB 16384
#define DD 512
#define HH 8192
#define KBK 16384

// ---------------- scratch ----------------
__device__ float g_exp[BB];
__device__ float g_bsum[KBK];
__device__ int   g_bcnt[KBK];
__device__ int   g_boff[KBK];      // master writes start; feeders advance to end
__device__ int2  g_pack[KBK];      // {sfx bits, start | cnt<<16}
__device__ int   g_perm[BB];
__device__ float g_con[HH];
__device__ float g_part[192];      // [0:64) num, [64:128) evs, [128:192) nll
__device__ int   g_cnt_done  = 0;
__device__ int   g_scan_done = 0;
__device__ int   g_scat_done = 0;

__device__ __forceinline__ int bucket_of(float t) {
    int b = (int)(t * 16384.0f);
    if (b < 0) b = 0;
    if (b > KBK - 1) b = KBK - 1;
    return b;
}

__device__ __forceinline__ float dot4(float4 x, float4 y) {
    return fmaf(x.x, y.x, fmaf(x.y, y.y, fmaf(x.z, y.z, x.w * y.w)));
}

// =====================================================================
// K1 (2049 x 512):
//   block 0      : master — wait feeders -> scan -> pack -> zero -> flag
//   blocks 1-64  : histogram -> contrast -> scatter -> scat_done++
//   blocks 65-128: contrast -> spin scat_done -> eval 256 elems -> partials
//   blocks 129+  : contrast only
// =====================================================================
__global__ __launch_bounds__(512) void k1_kernel(
    const float* __restrict__ r1, const float* __restrict__ r2,
    const float* __restrict__ r3,
    const float* __restrict__ hazard, const float* __restrict__ time_,
    const int* __restrict__ event, const float* __restrict__ score,
    const int* __restrict__ x1, const int* __restrict__ x2)
{
    int blk = blockIdx.x, tid = threadIdx.x;
    int lane = tid & 31, warp = tid >> 5;

    __shared__ float s_red[16][15];
    __shared__ int   s_ci[16];
    __shared__ float s_cf[16];

    if (blk == 0) {
        // ---- master: wait for the 64 histogram feeders ----
        if (tid == 0) {
            volatile int* p = &g_cnt_done;
            while (*p < 64) __nanosleep(64);
            g_cnt_done = 0;
        }
        __syncthreads();
        __threadfence();

        int base = warp * 1024;   // warp w owns buckets [w*1024, (w+1)*1024)

        // sweep A: warp totals
        int csum = 0; float fsum = 0.f;
        for (int r = 0; r < 32; r++) {
            int idx = base + r * 32 + lane;
            csum += g_bcnt[idx];
            fsum += g_bsum[idx];
        }
#pragma unroll
        for (int o = 16; o > 0; o >>= 1) {
            csum += __shfl_xor_sync(0xffffffffu, csum, o);
            fsum += __shfl_xor_sync(0xffffffffu, fsum, o);
        }
        if (lane == 0) { s_ci[warp] = csum; s_cf[warp] = fsum; }
        __syncthreads();

        int ibase = 0; float fsuf = 0.f;
        for (int w = 0; w < 16; w++) {
            if (w < warp) ibase += s_ci[w];
            if (w > warp) fsuf  += s_cf[w];
        }

        // sweep B: exclusive prefix of counts -> g_boff (start)
        int icarry = ibase;
        for (int r = 0; r < 32; r++) {
            int idx = base + r * 32 + lane;
            int c = g_bcnt[idx];
            int inc = c;
#pragma unroll
            for (int o = 1; o < 32; o <<= 1) {
                int u = __shfl_up_sync(0xffffffffu, inc, o);
                if (lane >= o) inc += u;
            }
            g_boff[idx] = icarry + inc - c;
            icarry += __shfl_sync(0xffffffffu, inc, 31);
        }

        // sweep C (reverse): strict suffix of bsum -> pack; zero scratch
        float fcarry = fsuf;
        for (int r = 31; r >= 0; r--) {
            int idx = base + r * 32 + lane;
            float v = g_bsum[idx];
            float incR = v;
#pragma unroll
            for (int o = 1; o < 32; o <<= 1) {
                float u = __shfl_down_sync(0xffffffffu, incR, o);
                if (lane < 32 - o) incR += u;
            }
            float sfx = fcarry + incR - v;
            int cnt   = g_bcnt[idx];
            int start = g_boff[idx];
            int2 pk;
            pk.x = __float_as_int(sfx);
            pk.y = start | (cnt << 16);
            g_pack[idx] = pk;
            g_bcnt[idx] = 0;
            g_bsum[idx] = 0.f;
            fcarry += __shfl_sync(0xffffffffu, incR, 0);
        }
        __syncthreads();
        __threadfence();
        if (tid == 0) g_scan_done = 1;
        return;
    }

    // ---- histogram feeders: blocks 1..64, 256 elements each ----
    if (blk <= 64) {
        if (tid < 256) {
            int i = (blk - 1) * 256 + tid;
            float e = expf(hazard[i]);
            g_exp[i] = e;
            int b = bucket_of(time_[i]);
            atomicAdd(&g_bsum[b], e);
            atomicAdd(&g_bcnt[b], 1);
        }
        __threadfence();
        __syncthreads();
        if (tid == 0) atomicAdd(&g_cnt_done, 1);
    }

    // ---- contrast: 4 pairs per block, 128 threads per pair ----
    {
        int group = tid >> 7, gt = tid & 127;
        int m = (blk - 1) * 4 + group;
        int a = x1[m], b = x2[m];

        const float4* A1 = (const float4*)(r1 + (size_t)a * DD);
        const float4* A2 = (const float4*)(r2 + (size_t)a * DD);
        const float4* A3 = (const float4*)(r3 + (size_t)a * DD);
        const float4* B1 = (const float4*)(r1 + (size_t)b * DD);
        const float4* B2 = (const float4*)(r2 + (size_t)b * DD);
        const float4* B3 = (const float4*)(r3 + (size_t)b * DD);

        float4 a1 = A1[gt], a2 = A2[gt], a3 = A3[gt];
        float4 b1 = B1[gt], b2 = B2[gt], b3 = B3[gt];

        float acc[15];
        acc[0]  = dot4(a1, a1);  acc[1]  = dot4(a2, a2);  acc[2]  = dot4(a3, a3);
        acc[3]  = dot4(b1, b1);  acc[4]  = dot4(b2, b2);  acc[5]  = dot4(b3, b3);
        acc[6]  = dot4(a1, a2);  acc[7]  = dot4(a1, a3);  acc[8]  = dot4(a2, a3);
        acc[9]  = dot4(b1, b2);  acc[10] = dot4(b1, b3);  acc[11] = dot4(b2, b3);
        acc[12] = dot4(a1, b1);  acc[13] = dot4(a2, b2);  acc[14] = dot4(a3, b3);

#pragma unroll
        for (int q = 0; q < 15; q++) {
            float v = acc[q];
#pragma unroll
            for (int o = 16; o > 0; o >>= 1) v += __shfl_xor_sync(0xffffffffu, v, o);
            if (lane == 0) s_red[warp][q] = v;
        }
        __syncthreads();

        if (gt == 0) {
            int w0 = group * 4;
            float s[15];
#pragma unroll
            for (int q = 0; q < 15; q++)
                s[q] = s_red[w0][q] + s_red[w0+1][q] + s_red[w0+2][q] + s_red[w0+3][q];

            const float EPS = 1e-8f;
            float n1a = fmaxf(sqrtf(s[0]), EPS), n2a = fmaxf(sqrtf(s[1]), EPS), n3a = fmaxf(sqrtf(s[2]), EPS);
            float n1b = fmaxf(sqrtf(s[3]), EPS), n2b = fmaxf(sqrtf(s[4]), EPS), n3b = fmaxf(sqrtf(s[5]), EPS);

            float dis_xx = s[6] / (n1a * n2a) + s[7]  / (n1a * n3a) + s[8]  / (n2a * n3a);
            float dis_yy = s[9] / (n1b * n2b) + s[10] / (n1b * n3b) + s[11] / (n2b * n3b);
            float dis_xy = s[12] / (n1a * n1b) + s[13] / (n2a * n2b) + s[14] / (n3a * n3b);

            float z = 0.2f + dis_xy - 0.5f * dis_xx - 0.5f * dis_yy;
            float sp = (z > 0.f) ? (z + log1pf(expf(-z))) : log1pf(expf(z));
            g_con[m] = sp;
        }
    }

    // ---- feeders: scatter after contrast (scan long done) ----
    if (blk <= 64) {
        if (tid == 0) {
            volatile int* p = &g_scan_done;
            while (*p == 0) __nanosleep(64);
        }
        __syncthreads();
        __threadfence();
        if (tid < 256) {
            int i = (blk - 1) * 256 + tid;
            int bkt = bucket_of(time_[i]);
            int slot = atomicAdd(&g_boff[bkt], 1);
            g_perm[slot] = i;
        }
        __threadfence();
        __syncthreads();
        if (tid == 0) atomicAdd(&g_scat_done, 1);
        return;
    }

    // ---- eval blocks 65..128: hidden under remaining contrast waves ----
    if (blk <= 128) {
        __shared__ float s_n[8], s_e[8], s_l[8];
        if (tid == 0) {
            volatile int* p = &g_scat_done;
            while (*p < 64) __nanosleep(64);
        }
        __syncthreads();
        __threadfence();

        int eb = blk - 65;             // 0..63
        if (tid < 256) {
            int i = eb * 256 + tid;
            float ti = time_[i];
            int bkt = bucket_of(ti);
            int2 pk = g_pack[bkt];
            float S = __int_as_float(pk.x) + g_exp[i];
            int start = pk.y & 0xffff;
            int cnt   = pk.y >> 16;
            if (cnt > 1) {
                for (int s = start; s < start + cnt; s++) {
                    int j = g_perm[s];
                    if (j == i) continue;
                    float tj = time_[j];
                    if (tj > ti || (tj == ti && j < i)) S += g_exp[j];
                }
            }
            float lr = logf(S + 1e-6f);
            int ev = event[i];
            float evf = (float)ev;
            float num = evf * (hazard[i] - lr);
            float evs = evf;
            float nll = score[2 * i + ev];

#pragma unroll
            for (int o = 16; o > 0; o >>= 1) {
                num += __shfl_xor_sync(0xffffffffu, num, o);
                evs += __shfl_xor_sync(0xffffffffu, evs, o);
                nll += __shfl_xor_sync(0xffffffffu, nll, o);
            }
            if (lane == 0) { s_n[warp] = num; s_e[warp] = evs; s_l[warp] = nll; }
        }
        __syncthreads();
        if (tid == 0) {
            float a = 0.f, b = 0.f, c = 0.f;
            for (int w = 0; w < 8; w++) { a += s_n[w]; b += s_e[w]; c += s_l[w]; }
            g_part[eb]        = a;
            g_part[64 + eb]   = b;
            g_part[128 + eb]  = c;
        }
    }
}

// =====================================================================
// K2 (1 x 512): deterministic finisher. Kernel boundary = sync.
// =====================================================================
__global__ __launch_bounds__(512) void k2_kernel(float* __restrict__ out) {
    __shared__ float s_c[16], s_n[16], s_e[16], s_l[16];
    int tid = threadIdx.x, lane = tid & 31, warp = tid >> 5;

    float cs = 0.f;
#pragma unroll
    for (int r = 0; r < 16; r++) cs += g_con[r * 512 + tid];

    float pn = 0.f, pe = 0.f, pl = 0.f;
    if (tid < 64) {
        pn = g_part[tid];
        pe = g_part[64 + tid];
        pl = g_part[128 + tid];
    }

#pragma unroll
    for (int o = 16; o > 0; o >>= 1) {
        cs += __shfl_xor_sync(0xffffffffu, cs, o);
        pn += __shfl_xor_sync(0xffffffffu, pn, o);
        pe += __shfl_xor_sync(0xffffffffu, pe, o);
        pl += __shfl_xor_sync(0xffffffffu, pl, o);
    }
    if (lane == 0) { s_c[warp] = cs; s_n[warp] = pn; s_e[warp] = pe; s_l[warp] = pl; }
    __syncthreads();

    if (tid == 0) {
        float CS = 0.f, PN = 0.f, PE = 0.f, PL = 0.f;
        for (int w = 0; w < 16; w++) {
            CS += s_c[w]; PN += s_n[w]; PE += s_e[w]; PL += s_l[w];
        }
        float nll_ = -PL / (float)BB;
        float cox  = -PN / (PE + 1e-6f);
        float con  = CS / (float)HH;
        out[0] = nll_ + cox + 0.3f * con;
        g_scan_done = 0;
        g_scat_done = 0;
    }
}

// ---------------- launch ----------------
extern "C" void kernel_launch(void* const* d_in, const int* in_sizes, int n_in,
                              void* d_out, int out_size) {
    const float* rep1   = (const float*)d_in[0];
    const float* rep2   = (const float*)d_in[1];
    const float* rep3   = (const float*)d_in[2];
    const float* hazard = (const float*)d_in[3];
    const float* score  = (const float*)d_in[4];
    const float* time_  = (const float*)d_in[5];
    const int*   event  = (const int*)d_in[6];
    const int*   x1_idx = (const int*)d_in[7];
    const int*   x2_idx = (const int*)d_in[8];
    float* out = (float*)d_out;

    k1_kernel<<<2049, 512>>>(rep1, rep2, rep3, hazard, time_,
                             event, score, x1_idx, x2_idx);
    k2_kernel<<<1, 512>>>(out);
}